// round 13
// baseline (speedup 1.0000x reference)
#include <cuda_runtime.h>
#include <cuda_bf16.h>
#include <cstdint>

#define B_   64
#define T_   2048
#define C_   64
#define H_   256
#define HOR_ 96
#define KP   704   // expanded K: 3*64 (x split) + 2*256 (spikes x w split)

// ---------------- scratch (device globals; no runtime allocation) ----------------
__device__ float g_cur[(size_t)B_ * T_ * H_];                       // 134 MB
__device__ __align__(16) __nv_bfloat16 g_Ae[(size_t)B_ * T_ * KP];  // 185 MB
__device__ __align__(16) __nv_bfloat16 g_Be[(size_t)3 * H_ * KP];   // 1.1 MB
__device__ float g_gx[(size_t)B_ * T_ * 3 * H_];                    // 403 MB
__device__ float g_hT[B_ * H_];

// ---------------- packed f32x2 helpers ----------------
__device__ __forceinline__ unsigned long long ffma2(unsigned long long a,
                                                    unsigned long long b,
                                                    unsigned long long c) {
    unsigned long long d;
    asm("fma.rn.f32x2 %0, %1, %2, %3;" : "=l"(d) : "l"(a), "l"(b), "l"(c));
    return d;
}
__device__ __forceinline__ float f2x_sum(unsigned long long v) {
    float lo = __uint_as_float((uint32_t)v);
    float hi = __uint_as_float((uint32_t)(v >> 32));
    return lo + hi;
}
__device__ __forceinline__ uint32_t smem_u32(const void* p) {
    uint32_t a;
    asm("{ .reg .u64 tt; cvta.to.shared.u64 tt, %1; cvt.u32.u64 %0, tt; }" : "=r"(a) : "l"(p));
    return a;
}

// ---------------- f32x2 GEMM (for cur = x @ snn_w^T; threshold-sensitive, stays fp32) ----------------
#define GSP 18

__global__ void __launch_bounds__(512, 1)
gemm_f32x2_kernel(const float* __restrict__ A, const float* __restrict__ Bw,
                  const float* __restrict__ bias, float* __restrict__ C,
                  int K, int N)
{
    __shared__ float As[2][128 * GSP];
    __shared__ float Bs[2][128 * GSP];

    const int tid = threadIdx.x;
    const int tx  = tid & 15;
    const int ty  = tid >> 4;
    const size_t m0 = (size_t)blockIdx.y * 128;
    const int    n0 = blockIdx.x * 128;

    const int lr = tid >> 2;
    const int lq = (tid & 3) * 4;
    const float* ag = A + (m0 + lr) * (size_t)K + lq;
    const float* bg = Bw + (size_t)(n0 + lr) * K + lq;
    const int sOff = lr * GSP + lq;

    unsigned long long acc[4][8];
#pragma unroll
    for (int i = 0; i < 4; i++)
#pragma unroll
        for (int j = 0; j < 8; j++) acc[i][j] = 0ull;

    const int NT = K >> 4;
    {
        float4 a0 = *(const float4*)(ag);
        float4 b0 = *(const float4*)(bg);
        float* da = &As[0][sOff];
        float* db = &Bs[0][sOff];
        *(float2*)(da + 0) = make_float2(a0.x, a0.y);
        *(float2*)(da + 2) = make_float2(a0.z, a0.w);
        *(float2*)(db + 0) = make_float2(b0.x, b0.y);
        *(float2*)(db + 2) = make_float2(b0.z, b0.w);
    }
    __syncthreads();

    for (int t = 0; t < NT; t++) {
        const int p = t & 1;
        const bool more = (t + 1 < NT);
        float4 na, nb;
        if (more) {
            na = *(const float4*)(ag + (t + 1) * 16);
            nb = *(const float4*)(bg + (t + 1) * 16);
        }
        const float* Ab = As[p];
        const float* Bb = Bs[p];
#pragma unroll
        for (int kp = 0; kp < 8; kp++) {
            unsigned long long af[4], bf[8];
#pragma unroll
            for (int i = 0; i < 4; i++)
                af[i] = *(const unsigned long long*)&Ab[(ty + 32 * i) * GSP + 2 * kp];
#pragma unroll
            for (int j = 0; j < 8; j++)
                bf[j] = *(const unsigned long long*)&Bb[(tx + 16 * j) * GSP + 2 * kp];
#pragma unroll
            for (int i = 0; i < 4; i++)
#pragma unroll
                for (int j = 0; j < 8; j++)
                    acc[i][j] = ffma2(af[i], bf[j], acc[i][j]);
        }
        if (more) {
            __syncthreads();
            float* da = &As[p ^ 1][sOff];
            float* db = &Bs[p ^ 1][sOff];
            *(float2*)(da + 0) = make_float2(na.x, na.y);
            *(float2*)(da + 2) = make_float2(na.z, na.w);
            *(float2*)(db + 0) = make_float2(nb.x, nb.y);
            *(float2*)(db + 2) = make_float2(nb.z, nb.w);
            __syncthreads();
        }
    }

    float bj[8];
#pragma unroll
    for (int j = 0; j < 8; j++) bj[j] = __ldg(&bias[n0 + tx + 16 * j]);
#pragma unroll
    for (int i = 0; i < 4; i++) {
        float* cr = C + (m0 + ty + 32 * i) * (size_t)N + n0 + tx;
#pragma unroll
        for (int j = 0; j < 8; j++)
            cr[16 * j] = f2x_sum(acc[i][j]) + bj[j];
    }
}

// ---------------- split-fp32 helpers ----------------
__device__ __forceinline__ void split_bf16(float x, __nv_bfloat16& hi, __nv_bfloat16& lo) {
    hi = __float2bfloat16(x);
    lo = __float2bfloat16(x - __bfloat162float(hi));
}
__device__ __forceinline__ uint32_t pack2(__nv_bfloat16 a, __nv_bfloat16 b) {
    return (uint32_t)__bfloat16_as_ushort(a) | ((uint32_t)__bfloat16_as_ushort(b) << 16);
}

// ---------------- x -> A' cols [0:192): [xhi | xlo | xhi] ----------------
__global__ void copyx_split_kernel(const float* __restrict__ x, __nv_bfloat16* __restrict__ Ae)
{
    int i   = blockIdx.x * 256 + threadIdx.x;   // float4 index over B*T*16
    int row = i >> 4;
    int c4  = (i & 15) * 4;
    float4 v = ((const float4*)x)[i];
    __nv_bfloat16 h0, l0, h1, l1, h2, l2, h3, l3;
    split_bf16(v.x, h0, l0); split_bf16(v.y, h1, l1);
    split_bf16(v.z, h2, l2); split_bf16(v.w, h3, l3);
    uint2 hiP = make_uint2(pack2(h0, h1), pack2(h2, h3));
    uint2 loP = make_uint2(pack2(l0, l1), pack2(l2, l3));
    __nv_bfloat16* dst = Ae + (size_t)row * KP;
    *(uint2*)(dst + c4)       = hiP;
    *(uint2*)(dst + 64 + c4)  = loP;
    *(uint2*)(dst + 128 + c4) = hiP;
}

// ---------------- LIF scan: spikes (exact in bf16) -> A' cols [192:448) and [448:704) ----------------
__global__ void lif_kernel(const float* __restrict__ cur, __nv_bfloat16* __restrict__ Ae)
{
    int b = blockIdx.x >> 1;
    int h = (blockIdx.x & 1) * 128 + threadIdx.x;
    const float* cp = cur + ((size_t)b * T_) * H_ + h;
    __nv_bfloat16* sp = Ae + ((size_t)b * T_) * KP + 192 + h;

    const __nv_bfloat16 one  = __float2bfloat16(1.0f);
    const __nv_bfloat16 zero = __float2bfloat16(0.0f);
    float mem = 0.f;
#pragma unroll 8
    for (int t = 0; t < T_; t++) {
        float iv = __ldg(cp); cp += H_;
        float reset = (mem > 1.0f) ? 1.0f : 0.0f;
        mem = __fsub_rn(__fadd_rn(__fmul_rn(0.9f, mem), iv), reset);
        __nv_bfloat16 spk = (mem > 1.0f) ? one : zero;
        sp[0]   = spk;
        sp[256] = spk;
        sp += KP;
    }
}

// ---------------- gru_wih -> B' [wxhi | wxhi | wxlo | wshi | wslo] ----------------
__global__ void wih_split_kernel(const float* __restrict__ wih, __nv_bfloat16* __restrict__ Be)
{
    int idx = blockIdx.x * 256 + threadIdx.x;   // over 768*320
    int n = idx / 320;
    int c = idx - n * 320;
    __nv_bfloat16 hi, lo;
    split_bf16(wih[idx], hi, lo);
    __nv_bfloat16* dst = Be + (size_t)n * KP;
    if (c < 64) { dst[c] = hi; dst[64 + c] = hi; dst[128 + c] = lo; }
    else        { int hh = c - 64; dst[192 + hh] = hi; dst[448 + hh] = lo; }
}

// ---------------- mma.sync bf16 GEMM with cp.async 4-stage pipeline ----------------
// gx[M,768] = A'[M,704] @ B'[768,704]^T + bih
#define MMS   40        // smem row stride in halves (32 + 8 pad)
#define MSTG  4
#define STG_H (128 * MMS)          // halves per stage (5120)
#define STG_B (STG_H * 2)          // bytes per stage (10240)
#define MMA_DSMEM (2 * MSTG * STG_B)  // 81920

__device__ __forceinline__ void ldsm_x4(uint32_t* r, uint32_t addr) {
    asm volatile("ldmatrix.sync.aligned.m8n8.x4.shared.b16 {%0,%1,%2,%3}, [%4];"
                 : "=r"(r[0]), "=r"(r[1]), "=r"(r[2]), "=r"(r[3]) : "r"(addr));
}
__device__ __forceinline__ void mma16816(float* c, const uint32_t* a, const uint32_t* b) {
    asm volatile("mma.sync.aligned.m16n8k16.row.col.f32.bf16.bf16.f32 "
                 "{%0,%1,%2,%3}, {%4,%5,%6,%7}, {%8,%9}, {%0,%1,%2,%3};"
                 : "+f"(c[0]), "+f"(c[1]), "+f"(c[2]), "+f"(c[3])
                 : "r"(a[0]), "r"(a[1]), "r"(a[2]), "r"(a[3]), "r"(b[0]), "r"(b[1]));
}
#define CP16(dst_u32, src_ptr) \
    asm volatile("cp.async.cg.shared.global [%0], [%1], 16;" :: "r"(dst_u32), "l"(src_ptr))
#define CP_COMMIT()  asm volatile("cp.async.commit_group;" ::: "memory")
#define CP_WAIT2()   asm volatile("cp.async.wait_group 2;" ::: "memory")

__global__ void __launch_bounds__(256, 2)
gemm_mma_kernel(const __nv_bfloat16* __restrict__ Ae, const __nv_bfloat16* __restrict__ Be,
                const float* __restrict__ bias, float* __restrict__ Cout)
{
    extern __shared__ __nv_bfloat16 dsm[];   // [A stages | B stages]

    const int tid  = threadIdx.x;
    const int lane = tid & 31;
    const int warp = tid >> 5;
    const int wm   = warp >> 2;
    const int wn   = warp & 3;
    const size_t m0 = (size_t)blockIdx.y * 128;
    const int    n0 = blockIdx.x * 128;

    const int lrow  = tid >> 1;
    const int lhalf = tid & 1;
    const uint4* agp = (const uint4*)(Ae + (m0 + lrow) * (size_t)KP) + lhalf * 2;
    const uint4* bgp = (const uint4*)(Be + (size_t)(n0 + lrow) * KP) + lhalf * 2;
    const uint32_t sByte = (uint32_t)(lrow * 5 + lhalf * 2) * 16;   // byte offset in stage

    const uint32_t aBase = smem_u32(dsm);
    const uint32_t bBase = aBase + MSTG * STG_B;

    const int arow_off = (wm * 64 + (lane & 15)) * MMS + (lane >> 4) * 8;
    const int brow_off = (wn * 32 + ((lane >> 4) & 1) * 8 + (lane & 7)) * MMS + ((lane >> 3) & 1) * 8;

    float acc[4][4][4];
#pragma unroll
    for (int mi = 0; mi < 4; mi++)
#pragma unroll
        for (int ni = 0; ni < 4; ni++)
#pragma unroll
            for (int f = 0; f < 4; f++) acc[mi][ni][f] = 0.f;

    const int NT = KP / 32;   // 22

    // prologue: stages 0..2
#pragma unroll
    for (int s = 0; s < MSTG - 1; s++) {
        uint32_t da = aBase + s * STG_B + sByte;
        uint32_t db = bBase + s * STG_B + sByte;
        CP16(da,      agp + s * 4);
        CP16(da + 16, agp + s * 4 + 1);
        CP16(db,      bgp + s * 4);
        CP16(db + 16, bgp + s * 4 + 1);
        CP_COMMIT();
    }

    for (int t = 0; t < NT; t++) {
        CP_WAIT2();
        __syncthreads();

        // issue stage t+3 (or an empty group to keep wait_group uniform)
        if (t + MSTG - 1 < NT) {
            const int s = (t + MSTG - 1) & (MSTG - 1);
            uint32_t da = aBase + s * STG_B + sByte;
            uint32_t db = bBase + s * STG_B + sByte;
            CP16(da,      agp + (t + MSTG - 1) * 4);
            CP16(da + 16, agp + (t + MSTG - 1) * 4 + 1);
            CP16(db,      bgp + (t + MSTG - 1) * 4);
            CP16(db + 16, bgp + (t + MSTG - 1) * 4 + 1);
        }
        CP_COMMIT();

        const int p = t & (MSTG - 1);
        const uint32_t aS = aBase + p * STG_B;
        const uint32_t bS = bBase + p * STG_B;
#pragma unroll
        for (int ks = 0; ks < 2; ks++) {
            uint32_t af[4][4], bf[2][4];
#pragma unroll
            for (int mi = 0; mi < 4; mi++)
                ldsm_x4(af[mi], aS + (uint32_t)(arow_off + mi * (16 * MMS) + ks * 16) * 2);
#pragma unroll
            for (int n2 = 0; n2 < 2; n2++)
                ldsm_x4(bf[n2], bS + (uint32_t)(brow_off + n2 * (16 * MMS) + ks * 16) * 2);
#pragma unroll
            for (int mi = 0; mi < 4; mi++)
#pragma unroll
                for (int ni = 0; ni < 4; ni++)
                    mma16816(acc[mi][ni], af[mi], &bf[ni >> 1][(ni & 1) * 2]);
        }
    }

#pragma unroll
    for (int ni = 0; ni < 4; ni++) {
        const int col = n0 + wn * 32 + ni * 8 + (lane & 3) * 2;
        float2 bv = *(const float2*)&bias[col];
#pragma unroll
        for (int mi = 0; mi < 4; mi++) {
            const size_t rlo = m0 + wm * 64 + mi * 16 + (lane >> 2);
            float2 o0, o1;
            o0.x = acc[mi][ni][0] + bv.x; o0.y = acc[mi][ni][1] + bv.y;
            o1.x = acc[mi][ni][2] + bv.x; o1.y = acc[mi][ni][3] + bv.y;
            *(float2*)&Cout[rlo * 768 + col]       = o0;
            *(float2*)&Cout[(rlo + 8) * 768 + col] = o1;
        }
    }
}

// ---------------- GRU scan v4: register weights + mbarrier cluster sync ----------------
// 4-CTA clusters, 2 batches/cluster, 384 threads. Per-step cluster barrier replaced by
// ping-pong DSMEM mbarriers: gate warps store h remotely, fence, elected arrive (count 32)
// at all 4 CTAs' mbar[t&1]; everyone try_waits parity (t>>1)&1. Expected 4*4*32 = 512.
__global__ void __cluster_dims__(4, 1, 1) __launch_bounds__(384, 1)
gru_kernel(const float* __restrict__ gx, const float* __restrict__ whh,
           const float* __restrict__ bhh, float* __restrict__ hT)
{
    __shared__ float shH[1024];    // [2 buf][2 batch][256]
    __shared__ float shRed[768];   // [slot*2 + b][64 jl]
    __shared__ __align__(8) unsigned long long mbar[2];

    const int tid  = threadIdx.x;
    const int rank = blockIdx.x & 3;
    const int b0   = (blockIdx.x >> 2) * 2;
    const int slot = tid >> 6;     // 0..5
    const int g    = slot >> 1;
    const int hk   = slot & 1;
    const int jl   = tid & 63;

    // time-invariant weights -> registers
    unsigned long long w[64];
    {
        const ulonglong2* wp = (const ulonglong2*)(
            whh + ((size_t)(g * 256 + rank * 64 + jl)) * 256 + hk * 128);
#pragma unroll
        for (int i = 0; i < 32; i++) {
            ulonglong2 v = wp[i];
            w[2 * i]     = v.x;
            w[2 * i + 1] = v.y;
        }
    }
    for (int idx = tid; idx < 1024; idx += 384) shH[idx] = 0.f;

    const uint32_t mb[2] = { smem_u32(&mbar[0]), smem_u32(&mbar[1]) };
    if (tid == 0) {
        asm volatile("mbarrier.init.shared.b64 [%0], %1;" :: "r"(mb[0]), "r"(512u) : "memory");
        asm volatile("mbarrier.init.shared.b64 [%0], %1;" :: "r"(mb[1]), "r"(512u) : "memory");
    }

    const bool isGate = (tid < 128);
    const int gb = (tid >> 6) & 1;
    const int gj = jl;

    float bh0 = 0.f, bh1 = 0.f, bh2 = 0.f;
    const float* gxp = nullptr;
    uint32_t hdst = 0;
    if (isGate) {
        bh0 = bhh[0 * 256 + rank * 64 + gj];
        bh1 = bhh[1 * 256 + rank * 64 + gj];
        bh2 = bhh[2 * 256 + rank * 64 + gj];
        gxp = gx + ((size_t)(b0 + gb) * T_) * 768 + rank * 64 + gj;
        hdst = smem_u32(&shH[gb * 256 + rank * 64 + gj]);   // base; +512 floats per buffer
    }

    __syncthreads();
    asm volatile("barrier.cluster.arrive.aligned;" ::: "memory");
    asm volatile("barrier.cluster.wait.aligned;" ::: "memory");

    int p = 0;
    for (int t = 0; t < T_; t++) {
        float xr = 0.f, xz = 0.f, xn = 0.f;
        if (isGate) {
            xr = __ldg(gxp);
            xz = __ldg(gxp + 256);
            xn = __ldg(gxp + 512);
        }

        const ulonglong2* hp0 = ((const ulonglong2*)shH) + p * 128 + 0 * 64 + hk * 32;
        const ulonglong2* hp1 = ((const ulonglong2*)shH) + p * 128 + 1 * 64 + hk * 32;

        unsigned long long a0 = 0ull, a0b = 0ull, a1 = 0ull, a1b = 0ull;
#pragma unroll
        for (int i = 0; i < 32; i++) {
            ulonglong2 h0 = hp0[i];
            ulonglong2 h1 = hp1[i];
            a0  = ffma2(w[2 * i],     h0.x, a0);
            a0b = ffma2(w[2 * i + 1], h0.y, a0b);
            a1  = ffma2(w[2 * i],     h1.x, a1);
            a1b = ffma2(w[2 * i + 1], h1.y, a1b);
        }
        shRed[(slot * 2 + 0) * 64 + jl] = f2x_sum(a0) + f2x_sum(a0b);
        shRed[(slot * 2 + 1) * 64 + jl] = f2x_sum(a1) + f2x_sum(a1b);
        __syncthreads();

        if (isGate) {
            float hr = shRed[(0 * 4 + gb) * 64 + gj] + shRed[(0 * 4 + 2 + gb) * 64 + gj];
            float hz = shRed[(1 * 4 + gb) * 64 + gj] + shRed[(1 * 4 + 2 + gb) * 64 + gj];
            float hn = shRed[(2 * 4 + gb) * 64 + gj] + shRed[(2 * 4 + 2 + gb) * 64 + gj];
            float hold = shH[p * 512 + gb * 256 + rank * 64 + gj];

            float r = 1.f / (1.f + expf(-(xr + hr + bh0)));
            float z = 1.f / (1.f + expf(-(xz + hz + bh1)));
            float n = tanhf(xn + r * (hn + bh2));
            float hnew = (1.f - z) * n + z * hold;

            const uint32_t laddr = hdst + (uint32_t)((p ^ 1) * 512) * 4;
#pragma unroll
            for (int rr = 0; rr < 4; rr++) {   // broadcast h_new to all cluster CTAs
                uint32_t ra;
                asm volatile("mapa.shared::cluster.u32 %0, %1, %2;"
                             : "=r"(ra) : "r"(laddr), "r"(rr));
                asm volatile("st.shared::cluster.f32 [%0], %1;" :: "r"(ra), "f"(hnew));
            }
            asm volatile("fence.acq_rel.cluster;" ::: "memory");
            __syncwarp();
            if ((tid & 31) == 0) {
                const uint32_t ml = mb[t & 1];
#pragma unroll
                for (int rr = 0; rr < 4; rr++) {
                    uint32_t ra;
                    asm volatile("mapa.shared::cluster.u32 %0, %1, %2;"
                                 : "=r"(ra) : "r"(ml), "r"(rr));
                    asm volatile(
                        "mbarrier.arrive.release.cluster.shared::cluster.b64 _, [%0], %1;"
                        :: "r"(ra), "r"(32u) : "memory");
                }
            }
            if (t == T_ - 1) hT[(b0 + gb) * 256 + rank * 64 + gj] = hnew;
            gxp += 768;
        }

        // all threads wait for this step's h broadcast (from all 4 CTAs)
        {
            const uint32_t ml = mb[t & 1];
            const uint32_t par = (uint32_t)((t >> 1) & 1);
            uint32_t done;
            asm volatile("{\n\t.reg .pred pq;\n\t"
                         "mbarrier.try_wait.parity.acquire.cta.shared::cta.b64 pq, [%1], %2;\n\t"
                         "selp.b32 %0, 1, 0, pq;\n\t}"
                         : "=r"(done) : "r"(ml), "r"(par) : "memory");
            if (!done) {
                asm volatile("{\n\t.reg .pred P1;\n\t"
                    "GWAIT_%=:\n\t"
                    "mbarrier.try_wait.parity.acquire.cta.shared::cta.b64 P1, [%0], %1, 0x989680;\n\t"
                    "@P1 bra.uni GDONE_%=;\n\t"
                    "bra.uni GWAIT_%=;\n\t"
                    "GDONE_%=:\n\t}"
                    :: "r"(ml), "r"(par) : "memory");
            }
            asm volatile("fence.acq_rel.cluster;" ::: "memory");
        }
        p ^= 1;
    }

    asm volatile("barrier.cluster.arrive.aligned;" ::: "memory");
    asm volatile("barrier.cluster.wait.aligned;" ::: "memory");
}

// ---------------- head ----------------
__global__ void head_kernel(const float* __restrict__ hT, const float* __restrict__ W,
                            const float* __restrict__ bias, float* __restrict__ out)
{
    int b = blockIdx.x;
    int o = threadIdx.x;   // 96 threads
    const float* h = hT + b * 256;
    const float* w = W + o * 256;
    float s = bias[o];
#pragma unroll 8
    for (int j = 0; j < 256; j++) s = fmaf(h[j], w[j], s);
    out[b * 96 + o] = s;
}

// ---------------- launch ----------------
extern "C" void kernel_launch(void* const* d_in, const int* in_sizes, int n_in,
                              void* d_out, int out_size)
{
    const float* x        = (const float*)d_in[0];
    const float* snn_w    = (const float*)d_in[1];
    const float* snn_b    = (const float*)d_in[2];
    const float* gru_wih  = (const float*)d_in[3];
    const float* gru_whh  = (const float*)d_in[4];
    const float* gru_bih  = (const float*)d_in[5];
    const float* gru_bhh  = (const float*)d_in[6];
    const float* head_w   = (const float*)d_in[7];
    const float* head_b   = (const float*)d_in[8];
    float* out = (float*)d_out;

    float *cur, *gxb, *hTb;
    __nv_bfloat16 *Ae, *Be;
    cudaGetSymbolAddress((void**)&cur, g_cur);
    cudaGetSymbolAddress((void**)&Ae,  g_Ae);
    cudaGetSymbolAddress((void**)&Be,  g_Be);
    cudaGetSymbolAddress((void**)&gxb, g_gx);
    cudaGetSymbolAddress((void**)&hTb, g_hT);

    cudaFuncSetAttribute(gemm_mma_kernel, cudaFuncAttributeMaxDynamicSharedMemorySize,
                         MMA_DSMEM);

    // 1) cur = x @ snn_w^T + snn_b   (fp32 f32x2 — spike thresholds are error-sensitive)
    gemm_f32x2_kernel<<<dim3(H_ / 128, (B_ * T_) / 128), 512>>>(x, snn_w, snn_b, cur, C_, H_);
    // 2) x -> A' split columns
    copyx_split_kernel<<<(B_ * T_ * 16) / 256, 256>>>(x, Ae);
    // 3) LIF scan -> A' spike columns (exact bf16)
    lif_kernel<<<128, 128>>>(cur, Ae);
    // 4) wih -> B' split columns
    wih_split_kernel<<<(768 * 320) / 256, 256>>>(gru_wih, Be);
    // 5) gx = A' @ B'^T + bih  (mma.sync bf16 HMMA, cp.async 4-stage)
    gemm_mma_kernel<<<dim3(768 / 128, (B_ * T_) / 128), 256, MMA_DSMEM>>>(Ae, Be, gru_bih, gxb);
    // 6) GRU scan (register weights + mbarrier cluster sync)
    gru_kernel<<<128, 384>>>(gxb, gru_whh, gru_bhh, hTb);
    // 7) head
    head_kernel<<<B_, HOR_>>>(hTb, head_w, head_b, out);
}

// round 14
// speedup vs baseline: 1.7352x; 1.7352x over previous
#include <cuda_runtime.h>
#include <cuda_bf16.h>
#include <cstdint>

#define B_   64
#define T_   2048
#define C_   64
#define H_   256
#define HOR_ 96
#define KP   704   // expanded K: 3*64 (x split) + 2*256 (spikes x w split)

// ---------------- scratch (device globals; no runtime allocation) ----------------
__device__ float g_cur[(size_t)B_ * T_ * H_];                       // 134 MB
__device__ __align__(16) __nv_bfloat16 g_Ae[(size_t)B_ * T_ * KP];  // 185 MB
__device__ __align__(16) __nv_bfloat16 g_Be[(size_t)3 * H_ * KP];   // 1.1 MB
__device__ float g_gx[(size_t)B_ * T_ * 3 * H_];                    // 403 MB
__device__ float g_hT[B_ * H_];

// ---------------- packed f32x2 helpers ----------------
__device__ __forceinline__ unsigned long long ffma2(unsigned long long a,
                                                    unsigned long long b,
                                                    unsigned long long c) {
    unsigned long long d;
    asm("fma.rn.f32x2 %0, %1, %2, %3;" : "=l"(d) : "l"(a), "l"(b), "l"(c));
    return d;
}
__device__ __forceinline__ float f2x_sum(unsigned long long v) {
    float lo = __uint_as_float((uint32_t)v);
    float hi = __uint_as_float((uint32_t)(v >> 32));
    return lo + hi;
}
__device__ __forceinline__ uint32_t smem_u32(const void* p) {
    uint32_t a;
    asm("{ .reg .u64 tt; cvta.to.shared.u64 tt, %1; cvt.u32.u64 %0, tt; }" : "=r"(a) : "l"(p));
    return a;
}

// ---------------- f32x2 GEMM (for cur = x @ snn_w^T; threshold-sensitive, stays fp32) ----------------
#define GSP 18

__global__ void __launch_bounds__(512, 1)
gemm_f32x2_kernel(const float* __restrict__ A, const float* __restrict__ Bw,
                  const float* __restrict__ bias, float* __restrict__ C,
                  int K, int N)
{
    __shared__ float As[2][128 * GSP];
    __shared__ float Bs[2][128 * GSP];

    const int tid = threadIdx.x;
    const int tx  = tid & 15;
    const int ty  = tid >> 4;
    const size_t m0 = (size_t)blockIdx.y * 128;
    const int    n0 = blockIdx.x * 128;

    const int lr = tid >> 2;
    const int lq = (tid & 3) * 4;
    const float* ag = A + (m0 + lr) * (size_t)K + lq;
    const float* bg = Bw + (size_t)(n0 + lr) * K + lq;
    const int sOff = lr * GSP + lq;

    unsigned long long acc[4][8];
#pragma unroll
    for (int i = 0; i < 4; i++)
#pragma unroll
        for (int j = 0; j < 8; j++) acc[i][j] = 0ull;

    const int NT = K >> 4;
    {
        float4 a0 = *(const float4*)(ag);
        float4 b0 = *(const float4*)(bg);
        float* da = &As[0][sOff];
        float* db = &Bs[0][sOff];
        *(float2*)(da + 0) = make_float2(a0.x, a0.y);
        *(float2*)(da + 2) = make_float2(a0.z, a0.w);
        *(float2*)(db + 0) = make_float2(b0.x, b0.y);
        *(float2*)(db + 2) = make_float2(b0.z, b0.w);
    }
    __syncthreads();

    for (int t = 0; t < NT; t++) {
        const int p = t & 1;
        const bool more = (t + 1 < NT);
        float4 na, nb;
        if (more) {
            na = *(const float4*)(ag + (t + 1) * 16);
            nb = *(const float4*)(bg + (t + 1) * 16);
        }
        const float* Ab = As[p];
        const float* Bb = Bs[p];
#pragma unroll
        for (int kp = 0; kp < 8; kp++) {
            unsigned long long af[4], bf[8];
#pragma unroll
            for (int i = 0; i < 4; i++)
                af[i] = *(const unsigned long long*)&Ab[(ty + 32 * i) * GSP + 2 * kp];
#pragma unroll
            for (int j = 0; j < 8; j++)
                bf[j] = *(const unsigned long long*)&Bb[(tx + 16 * j) * GSP + 2 * kp];
#pragma unroll
            for (int i = 0; i < 4; i++)
#pragma unroll
                for (int j = 0; j < 8; j++)
                    acc[i][j] = ffma2(af[i], bf[j], acc[i][j]);
        }
        if (more) {
            __syncthreads();
            float* da = &As[p ^ 1][sOff];
            float* db = &Bs[p ^ 1][sOff];
            *(float2*)(da + 0) = make_float2(na.x, na.y);
            *(float2*)(da + 2) = make_float2(na.z, na.w);
            *(float2*)(db + 0) = make_float2(nb.x, nb.y);
            *(float2*)(db + 2) = make_float2(nb.z, nb.w);
            __syncthreads();
        }
    }

    float bj[8];
#pragma unroll
    for (int j = 0; j < 8; j++) bj[j] = __ldg(&bias[n0 + tx + 16 * j]);
#pragma unroll
    for (int i = 0; i < 4; i++) {
        float* cr = C + (m0 + ty + 32 * i) * (size_t)N + n0 + tx;
#pragma unroll
        for (int j = 0; j < 8; j++)
            cr[16 * j] = f2x_sum(acc[i][j]) + bj[j];
    }
}

// ---------------- split-fp32 helpers ----------------
__device__ __forceinline__ void split_bf16(float x, __nv_bfloat16& hi, __nv_bfloat16& lo) {
    hi = __float2bfloat16(x);
    lo = __float2bfloat16(x - __bfloat162float(hi));
}
__device__ __forceinline__ uint32_t pack2(__nv_bfloat16 a, __nv_bfloat16 b) {
    return (uint32_t)__bfloat16_as_ushort(a) | ((uint32_t)__bfloat16_as_ushort(b) << 16);
}

// ---------------- x -> A' cols [0:192): [xhi | xlo | xhi] ----------------
__global__ void copyx_split_kernel(const float* __restrict__ x, __nv_bfloat16* __restrict__ Ae)
{
    int i   = blockIdx.x * 256 + threadIdx.x;   // float4 index over B*T*16
    int row = i >> 4;
    int c4  = (i & 15) * 4;
    float4 v = ((const float4*)x)[i];
    __nv_bfloat16 h0, l0, h1, l1, h2, l2, h3, l3;
    split_bf16(v.x, h0, l0); split_bf16(v.y, h1, l1);
    split_bf16(v.z, h2, l2); split_bf16(v.w, h3, l3);
    uint2 hiP = make_uint2(pack2(h0, h1), pack2(h2, h3));
    uint2 loP = make_uint2(pack2(l0, l1), pack2(l2, l3));
    __nv_bfloat16* dst = Ae + (size_t)row * KP;
    *(uint2*)(dst + c4)       = hiP;
    *(uint2*)(dst + 64 + c4)  = loP;
    *(uint2*)(dst + 128 + c4) = hiP;
}

// ---------------- LIF scan: spikes (exact in bf16) -> A' cols [192:448) and [448:704) ----------------
__global__ void lif_kernel(const float* __restrict__ cur, __nv_bfloat16* __restrict__ Ae)
{
    int b = blockIdx.x >> 1;
    int h = (blockIdx.x & 1) * 128 + threadIdx.x;
    const float* cp = cur + ((size_t)b * T_) * H_ + h;
    __nv_bfloat16* sp = Ae + ((size_t)b * T_) * KP + 192 + h;

    const __nv_bfloat16 one  = __float2bfloat16(1.0f);
    const __nv_bfloat16 zero = __float2bfloat16(0.0f);
    float mem = 0.f;
#pragma unroll 8
    for (int t = 0; t < T_; t++) {
        float iv = __ldg(cp); cp += H_;
        float reset = (mem > 1.0f) ? 1.0f : 0.0f;
        mem = __fsub_rn(__fadd_rn(__fmul_rn(0.9f, mem), iv), reset);
        __nv_bfloat16 spk = (mem > 1.0f) ? one : zero;
        sp[0]   = spk;
        sp[256] = spk;
        sp += KP;
    }
}

// ---------------- gru_wih -> B' [wxhi | wxhi | wxlo | wshi | wslo] ----------------
__global__ void wih_split_kernel(const float* __restrict__ wih, __nv_bfloat16* __restrict__ Be)
{
    int idx = blockIdx.x * 256 + threadIdx.x;   // over 768*320
    int n = idx / 320;
    int c = idx - n * 320;
    __nv_bfloat16 hi, lo;
    split_bf16(wih[idx], hi, lo);
    __nv_bfloat16* dst = Be + (size_t)n * KP;
    if (c < 64) { dst[c] = hi; dst[64 + c] = hi; dst[128 + c] = lo; }
    else        { int hh = c - 64; dst[192 + hh] = hi; dst[448 + hh] = lo; }
}

// ---------------- mma.sync bf16 GEMM with cp.async 4-stage pipeline ----------------
// gx[M,768] = A'[M,704] @ B'[768,704]^T + bih
#define MMS   40        // smem row stride in halves (32 + 8 pad)
#define MSTG  4
#define STG_H (128 * MMS)          // halves per stage (5120)
#define STG_B (STG_H * 2)          // bytes per stage (10240)
#define MMA_DSMEM (2 * MSTG * STG_B)  // 81920

__device__ __forceinline__ void ldsm_x4(uint32_t* r, uint32_t addr) {
    asm volatile("ldmatrix.sync.aligned.m8n8.x4.shared.b16 {%0,%1,%2,%3}, [%4];"
                 : "=r"(r[0]), "=r"(r[1]), "=r"(r[2]), "=r"(r[3]) : "r"(addr));
}
__device__ __forceinline__ void mma16816(float* c, const uint32_t* a, const uint32_t* b) {
    asm volatile("mma.sync.aligned.m16n8k16.row.col.f32.bf16.bf16.f32 "
                 "{%0,%1,%2,%3}, {%4,%5,%6,%7}, {%8,%9}, {%0,%1,%2,%3};"
                 : "+f"(c[0]), "+f"(c[1]), "+f"(c[2]), "+f"(c[3])
                 : "r"(a[0]), "r"(a[1]), "r"(a[2]), "r"(a[3]), "r"(b[0]), "r"(b[1]));
}
#define CP16(dst_u32, src_ptr) \
    asm volatile("cp.async.cg.shared.global [%0], [%1], 16;" :: "r"(dst_u32), "l"(src_ptr))
#define CP_COMMIT()  asm volatile("cp.async.commit_group;" ::: "memory")
#define CP_WAIT2()   asm volatile("cp.async.wait_group 2;" ::: "memory")

__global__ void __launch_bounds__(256, 2)
gemm_mma_kernel(const __nv_bfloat16* __restrict__ Ae, const __nv_bfloat16* __restrict__ Be,
                const float* __restrict__ bias, float* __restrict__ Cout)
{
    extern __shared__ __nv_bfloat16 dsm[];   // [A stages | B stages]

    const int tid  = threadIdx.x;
    const int lane = tid & 31;
    const int warp = tid >> 5;
    const int wm   = warp >> 2;
    const int wn   = warp & 3;
    const size_t m0 = (size_t)blockIdx.y * 128;
    const int    n0 = blockIdx.x * 128;

    const int lrow  = tid >> 1;
    const int lhalf = tid & 1;
    const uint4* agp = (const uint4*)(Ae + (m0 + lrow) * (size_t)KP) + lhalf * 2;
    const uint4* bgp = (const uint4*)(Be + (size_t)(n0 + lrow) * KP) + lhalf * 2;
    const uint32_t sByte = (uint32_t)(lrow * 5 + lhalf * 2) * 16;   // byte offset in stage

    const uint32_t aBase = smem_u32(dsm);
    const uint32_t bBase = aBase + MSTG * STG_B;

    const int arow_off = (wm * 64 + (lane & 15)) * MMS + (lane >> 4) * 8;
    const int brow_off = (wn * 32 + ((lane >> 4) & 1) * 8 + (lane & 7)) * MMS + ((lane >> 3) & 1) * 8;

    float acc[4][4][4];
#pragma unroll
    for (int mi = 0; mi < 4; mi++)
#pragma unroll
        for (int ni = 0; ni < 4; ni++)
#pragma unroll
            for (int f = 0; f < 4; f++) acc[mi][ni][f] = 0.f;

    const int NT = KP / 32;   // 22

    // prologue: stages 0..2
#pragma unroll
    for (int s = 0; s < MSTG - 1; s++) {
        uint32_t da = aBase + s * STG_B + sByte;
        uint32_t db = bBase + s * STG_B + sByte;
        CP16(da,      agp + s * 4);
        CP16(da + 16, agp + s * 4 + 1);
        CP16(db,      bgp + s * 4);
        CP16(db + 16, bgp + s * 4 + 1);
        CP_COMMIT();
    }

    for (int t = 0; t < NT; t++) {
        CP_WAIT2();
        __syncthreads();

        // issue stage t+3 (or an empty group to keep wait_group count uniform)
        if (t + MSTG - 1 < NT) {
            const int s = (t + MSTG - 1) & (MSTG - 1);
            uint32_t da = aBase + s * STG_B + sByte;
            uint32_t db = bBase + s * STG_B + sByte;
            CP16(da,      agp + (t + MSTG - 1) * 4);
            CP16(da + 16, agp + (t + MSTG - 1) * 4 + 1);
            CP16(db,      bgp + (t + MSTG - 1) * 4);
            CP16(db + 16, bgp + (t + MSTG - 1) * 4 + 1);
        }
        CP_COMMIT();

        const int p = t & (MSTG - 1);
        const uint32_t aS = aBase + p * STG_B;
        const uint32_t bS = bBase + p * STG_B;
#pragma unroll
        for (int ks = 0; ks < 2; ks++) {
            uint32_t af[4][4], bf[2][4];
#pragma unroll
            for (int mi = 0; mi < 4; mi++)
                ldsm_x4(af[mi], aS + (uint32_t)(arow_off + mi * (16 * MMS) + ks * 16) * 2);
#pragma unroll
            for (int n2 = 0; n2 < 2; n2++)
                ldsm_x4(bf[n2], bS + (uint32_t)(brow_off + n2 * (16 * MMS) + ks * 16) * 2);
#pragma unroll
            for (int mi = 0; mi < 4; mi++)
#pragma unroll
                for (int ni = 0; ni < 4; ni++)
                    mma16816(acc[mi][ni], af[mi], &bf[ni >> 1][(ni & 1) * 2]);
        }
    }

#pragma unroll
    for (int ni = 0; ni < 4; ni++) {
        const int col = n0 + wn * 32 + ni * 8 + (lane & 3) * 2;
        float2 bv = *(const float2*)&bias[col];
#pragma unroll
        for (int mi = 0; mi < 4; mi++) {
            const size_t rlo = m0 + wm * 64 + mi * 16 + (lane >> 2);
            float2 o0, o1;
            o0.x = acc[mi][ni][0] + bv.x; o0.y = acc[mi][ni][1] + bv.y;
            o1.x = acc[mi][ni][2] + bv.x; o1.y = acc[mi][ni][3] + bv.y;
            *(float2*)&Cout[rlo * 768 + col]       = o0;
            *(float2*)&Cout[(rlo + 8) * 768 + col] = o1;
        }
    }
}

// ---------------- GRU scan v3 (R12, proven): 4-CTA clusters, 2 batches, weights in REGISTERS ----------------
__global__ void __cluster_dims__(4, 1, 1) __launch_bounds__(384, 1)
gru_kernel(const float* __restrict__ gx, const float* __restrict__ whh,
           const float* __restrict__ bhh, float* __restrict__ hT)
{
    __shared__ float shH[1024];    // [2 buf][2 batch][256]
    __shared__ float shRed[768];   // [slot*2 + b][64 jl]

    const int tid  = threadIdx.x;
    const int rank = blockIdx.x & 3;
    const int b0   = (blockIdx.x >> 2) * 2;
    const int slot = tid >> 6;     // 0..5
    const int g    = slot >> 1;
    const int hk   = slot & 1;
    const int jl   = tid & 63;

    // time-invariant weights -> registers (64 f32x2 = this thread's 128-k row-half)
    unsigned long long w[64];
    {
        const ulonglong2* wp = (const ulonglong2*)(
            whh + ((size_t)(g * 256 + rank * 64 + jl)) * 256 + hk * 128);
#pragma unroll
        for (int i = 0; i < 32; i++) {
            ulonglong2 v = wp[i];
            w[2 * i]     = v.x;
            w[2 * i + 1] = v.y;
        }
    }
    for (int idx = tid; idx < 1024; idx += 384) shH[idx] = 0.f;

    const bool isGate = (tid < 128);
    const int gb = (tid >> 6) & 1;     // batch for gate stage (valid when isGate)
    const int gj = jl;

    float bh0 = 0.f, bh1 = 0.f, bh2 = 0.f;
    const float* gxp = nullptr;
    if (isGate) {
        bh0 = bhh[0 * 256 + rank * 64 + gj];
        bh1 = bhh[1 * 256 + rank * 64 + gj];
        bh2 = bhh[2 * 256 + rank * 64 + gj];
        gxp = gx + ((size_t)(b0 + gb) * T_) * 768 + rank * 64 + gj;
    }

    __syncthreads();
    asm volatile("barrier.cluster.arrive.aligned;" ::: "memory");
    asm volatile("barrier.cluster.wait.aligned;" ::: "memory");

    int p = 0;
    for (int t = 0; t < T_; t++) {
        float xr = 0.f, xz = 0.f, xn = 0.f;
        if (isGate) {                  // issue early; consumed after dot loop
            xr = __ldg(gxp);
            xz = __ldg(gxp + 256);
            xn = __ldg(gxp + 512);
        }

        // h slices for both batches: 32 x 16B broadcast loads each
        const ulonglong2* hp0 = ((const ulonglong2*)shH) + p * 128 + 0 * 64 + hk * 32;
        const ulonglong2* hp1 = ((const ulonglong2*)shH) + p * 128 + 1 * 64 + hk * 32;

        unsigned long long a0 = 0ull, a0b = 0ull, a1 = 0ull, a1b = 0ull;
#pragma unroll
        for (int i = 0; i < 32; i++) {
            ulonglong2 h0 = hp0[i];
            ulonglong2 h1 = hp1[i];
            a0  = ffma2(w[2 * i],     h0.x, a0);
            a0b = ffma2(w[2 * i + 1], h0.y, a0b);
            a1  = ffma2(w[2 * i],     h1.x, a1);
            a1b = ffma2(w[2 * i + 1], h1.y, a1b);
        }
        shRed[(slot * 2 + 0) * 64 + jl] = f2x_sum(a0) + f2x_sum(a0b);
        shRed[(slot * 2 + 1) * 64 + jl] = f2x_sum(a1) + f2x_sum(a1b);
        __syncthreads();

        if (isGate) {
            float hr = shRed[(0 * 4 + gb) * 64 + gj] + shRed[(0 * 4 + 2 + gb) * 64 + gj];
            float hz = shRed[(1 * 4 + gb) * 64 + gj] + shRed[(1 * 4 + 2 + gb) * 64 + gj];
            float hn = shRed[(2 * 4 + gb) * 64 + gj] + shRed[(2 * 4 + 2 + gb) * 64 + gj];
            float hold = shH[p * 512 + gb * 256 + rank * 64 + gj];

            float r = 1.f / (1.f + expf(-(xr + hr + bh0)));
            float z = 1.f / (1.f + expf(-(xz + hz + bh1)));
            float n = tanhf(xn + r * (hn + bh2));
            float hnew = (1.f - z) * n + z * hold;

            uint32_t laddr;
            {
                const float* pdst = &shH[(p ^ 1) * 512 + gb * 256 + rank * 64 + gj];
                asm("{ .reg .u64 tt; cvta.to.shared.u64 tt, %1; cvt.u32.u64 %0, tt; }"
                    : "=r"(laddr) : "l"(pdst));
            }
#pragma unroll
            for (int rr = 0; rr < 4; rr++) {   // broadcast h_new to all cluster CTAs
                uint32_t ra;
                asm volatile("mapa.shared::cluster.u32 %0, %1, %2;"
                             : "=r"(ra) : "r"(laddr), "r"(rr));
                asm volatile("st.shared::cluster.f32 [%0], %1;" :: "r"(ra), "f"(hnew));
            }
            if (t == T_ - 1) hT[(b0 + gb) * 256 + rank * 64 + gj] = hnew;
            gxp += 768;
        }

        asm volatile("barrier.cluster.arrive.aligned;" ::: "memory");
        asm volatile("barrier.cluster.wait.aligned;" ::: "memory");
        p ^= 1;
    }
}

// ---------------- head ----------------
__global__ void head_kernel(const float* __restrict__ hT, const float* __restrict__ W,
                            const float* __restrict__ bias, float* __restrict__ out)
{
    int b = blockIdx.x;
    int o = threadIdx.x;   // 96 threads
    const float* h = hT + b * 256;
    const float* w = W + o * 256;
    float s = bias[o];
#pragma unroll 8
    for (int j = 0; j < 256; j++) s = fmaf(h[j], w[j], s);
    out[b * 96 + o] = s;
}

// ---------------- launch ----------------
extern "C" void kernel_launch(void* const* d_in, const int* in_sizes, int n_in,
                              void* d_out, int out_size)
{
    const float* x        = (const float*)d_in[0];
    const float* snn_w    = (const float*)d_in[1];
    const float* snn_b    = (const float*)d_in[2];
    const float* gru_wih  = (const float*)d_in[3];
    const float* gru_whh  = (const float*)d_in[4];
    const float* gru_bih  = (const float*)d_in[5];
    const float* gru_bhh  = (const float*)d_in[6];
    const float* head_w   = (const float*)d_in[7];
    const float* head_b   = (const float*)d_in[8];
    float* out = (float*)d_out;

    float *cur, *gxb, *hTb;
    __nv_bfloat16 *Ae, *Be;
    cudaGetSymbolAddress((void**)&cur, g_cur);
    cudaGetSymbolAddress((void**)&Ae,  g_Ae);
    cudaGetSymbolAddress((void**)&Be,  g_Be);
    cudaGetSymbolAddress((void**)&gxb, g_gx);
    cudaGetSymbolAddress((void**)&hTb, g_hT);

    cudaFuncSetAttribute(gemm_mma_kernel, cudaFuncAttributeMaxDynamicSharedMemorySize,
                         MMA_DSMEM);

    // 1) cur = x @ snn_w^T + snn_b   (fp32 f32x2 — spike thresholds are error-sensitive)
    gemm_f32x2_kernel<<<dim3(H_ / 128, (B_ * T_) / 128), 512>>>(x, snn_w, snn_b, cur, C_, H_);
    // 2) x -> A' split columns
    copyx_split_kernel<<<(B_ * T_ * 16) / 256, 256>>>(x, Ae);
    // 3) LIF scan -> A' spike columns (exact bf16)
    lif_kernel<<<128, 128>>>(cur, Ae);
    // 4) wih -> B' split columns
    wih_split_kernel<<<(768 * 320) / 256, 256>>>(gru_wih, Be);
    // 5) gx = A' @ B'^T + bih  (mma.sync bf16 HMMA, cp.async 4-stage)
    gemm_mma_kernel<<<dim3(768 / 128, (B_ * T_) / 128), 256, MMA_DSMEM>>>(Ae, Be, gru_bih, gxb);
    // 6) GRU scan (R12 proven: register weights + cluster.sync)
    gru_kernel<<<128, 384>>>(gxb, gru_whh, gru_bhh, hTb);
    // 7) head
    head_kernel<<<B_, HOR_>>>(hTb, head_w, head_b, out);
}